// round 12
// baseline (speedup 1.0000x reference)
#include <cuda_runtime.h>
#include <cuda_fp16.h>
#include <cuda_fp8.h>
#include <cstdint>

// ============================================================================
// CrystalAttention, sm_100-baseline ISA (mma.sync + cp.async; no tcgen05).
//   VWt[d][n] = sum_k W[d,k] V[n,k]
//   S = X @ P^T ; E = exp(scales/(sqrt(max(xsq+psq-2S,0))+0.1))
//   out = (E @ VWt^T) / rowsum(E) + b_out
// M=16384, D=512, N=1024.
// R12: GEMM-E in fp8 e4m3 (m16n8k32, f32 acc; positions pre-scaled x16,
// epilogue uses -0.125*S'). GEMM-out / VWt stay fp16 f16-accum (R11 core).
// ============================================================================
#define MTOT 16384
#define DIM  512
#define NNEU 1024

__device__ uint8_t g_x8[(size_t)MTOT * DIM];   // x e4m3
__device__ float   g_xsq[MTOT];
__device__ uint8_t g_p8[(size_t)NNEU * DIM];   // positions*16 e4m3
__device__ float   g_psq[NNEU];
__device__ __half  g_vb[(size_t)NNEU * DIM];
__device__ __half  g_wb[(size_t)DIM * DIM];
__device__ __half  g_vwt[(size_t)DIM * NNEU];
__device__ __half  g_E[(size_t)MTOT * NNEU];
__device__ float   g_rsp[(size_t)MTOT * 8];    // partial rowsums per nb

// ============================================================================
// helpers
// ============================================================================
__device__ __forceinline__ uint32_t smem_u32(const void* p) {
    uint32_t a;
    asm("{ .reg .u64 t; cvta.to.shared.u64 t, %1; cvt.u32.u64 %0, t; }"
        : "=r"(a) : "l"(p));
    return a;
}

#define CP_ASYNC16(saddr, gaddr) \
    asm volatile("cp.async.cg.shared.global [%0], [%1], 16;\n" \
                 :: "r"(saddr), "l"(gaddr) : "memory")
#define CP_COMMIT() asm volatile("cp.async.commit_group;\n" ::: "memory")
#define CP_WAIT(n)  asm volatile("cp.async.wait_group %0;\n" :: "n"(n) : "memory")

__device__ __forceinline__ void ldsm_x4(uint32_t* f, uint32_t addr) {
    asm volatile("ldmatrix.sync.aligned.m8n8.x4.shared.b16 {%0,%1,%2,%3}, [%4];\n"
                 : "=r"(f[0]), "=r"(f[1]), "=r"(f[2]), "=r"(f[3]) : "r"(addr));
}

// f16-accumulate MMA: D(f16x2 x2) = A(f16 x4) * B(f16 x2) + D
__device__ __forceinline__ void mma16816_f16(uint32_t* d, const uint32_t* a,
                                             const uint32_t* b) {
    asm volatile(
        "mma.sync.aligned.m16n8k16.row.col.f16.f16.f16.f16 "
        "{%0,%1}, {%2,%3,%4,%5}, {%6,%7}, {%0,%1};\n"
        : "+r"(d[0]), "+r"(d[1])
        : "r"(a[0]), "r"(a[1]), "r"(a[2]), "r"(a[3]), "r"(b[0]), "r"(b[1]));
}

// fp8 e4m3 MMA, k32, f32 accumulate
__device__ __forceinline__ void mma16832_e4m3(float* d, const uint32_t* a,
                                              const uint32_t* b) {
    asm volatile(
        "mma.sync.aligned.m16n8k32.row.col.f32.e4m3.e4m3.f32 "
        "{%0,%1,%2,%3}, {%4,%5,%6,%7}, {%8,%9}, {%0,%1,%2,%3};\n"
        : "+f"(d[0]), "+f"(d[1]), "+f"(d[2]), "+f"(d[3])
        : "r"(a[0]), "r"(a[1]), "r"(a[2]), "r"(a[3]), "r"(b[0]), "r"(b[1]));
}

// swizzled smem byte offset, 128B pitch rows, b16 col c (c%8==0)
__device__ __forceinline__ uint32_t sw_off(int r, int c) {
    return (uint32_t)(r * 128 + ((((c >> 3) ^ (r & 7))) << 4));
}

__device__ __forceinline__ uint32_t f4_to_e4m3x4(float4 v, float scl) {
    __nv_fp8x2_storage_t lo = __nv_cvt_float2_to_fp8x2(
        make_float2(v.x * scl, v.y * scl), __NV_SATFINITE, __NV_E4M3);
    __nv_fp8x2_storage_t hi = __nv_cvt_float2_to_fp8x2(
        make_float2(v.z * scl, v.w * scl), __NV_SATFINITE, __NV_E4M3);
    return (uint32_t)lo | ((uint32_t)hi << 16);
}

// ============================================================================
// prep: fp32 -> e4m3 + row sum-of-squares. One warp per row. positions x16.
// ============================================================================
__global__ void k_rowsq(const float* __restrict__ x, const float* __restrict__ pos) {
    int gw = blockIdx.x * 8 + (threadIdx.x >> 5);
    int lane = threadIdx.x & 31;
    const float* src;
    uint8_t* dstB;
    float* dstS;
    int r;
    float scl;
    if (gw < MTOT) { src = x;   dstB = g_x8; dstS = g_xsq; r = gw;        scl = 1.f;  }
    else           { src = pos; dstB = g_p8; dstS = g_psq; r = gw - MTOT; scl = 16.f; }

    const float4* p = reinterpret_cast<const float4*>(src) + (size_t)r * (DIM / 4);
    uint32_t* q = reinterpret_cast<uint32_t*>(dstB + (size_t)r * DIM);
    float s = 0.f;
    #pragma unroll
    for (int i = 0; i < 4; i++) {
        float4 v = p[lane + 32 * i];
        q[lane + 32 * i] = f4_to_e4m3x4(v, scl);
        s += v.x * v.x + v.y * v.y + v.z * v.z + v.w * v.w;
    }
    #pragma unroll
    for (int off = 16; off > 0; off >>= 1)
        s += __shfl_xor_sync(0xffffffffu, s, off);
    if (lane == 0) dstS[r] = s;   // sum of squares of UNscaled values
}

// prep: fp32->fp16 for values then W_out, one grid
__global__ void k_conv(const float* __restrict__ values, const float* __restrict__ W) {
    constexpr int NV4 = (NNEU * DIM) / 4;   // 131072
    int i = blockIdx.x * blockDim.x + threadIdx.x;
    const float* src;
    __half* dst;
    int j;
    if (i < NV4) { src = values; dst = g_vb; j = i; }
    else         { src = W;      dst = g_wb; j = i - NV4; }
    float4 v = reinterpret_cast<const float4*>(src)[j];
    __half2 p0 = __floats2half2_rn(v.x, v.y);
    __half2 p1 = __floats2half2_rn(v.z, v.w);
    uint2 u;
    u.x = *reinterpret_cast<uint32_t*>(&p0);
    u.y = *reinterpret_cast<uint32_t*>(&p1);
    reinterpret_cast<uint2*>(dst)[j] = u;
}

// ============================================================================
// shared pipeline constants
// ============================================================================
constexpr int STG    = 32768;            // bytes per stage (A 16KB + B 16KB)
constexpr int SM_RS  = 2 * STG;          // rowsum scratch (128*2 floats)
constexpr int SMEM_SZ = SM_RS + 1024;    // 66560 B/CTA

// ============================================================================
// fp8 score GEMM: S' = X8 @ P8^T (e4m3, k-chunk 128 bytes, 4 x k32 MMA).
// CTA tile 128x128, 256 thr, warps 4(M)x2(N), warp tile 32x64, f32 acc.
// Epilogue: E = exp(scl/(sqrt(max(xsq+psq-0.125*S',0))+0.1)), f16 store +
// partial rowsum to g_rsp. 2 CTAs/SM.
// ============================================================================
__global__ void __launch_bounds__(256, 2) k_scores8(
    const float* __restrict__ xsq,
    const float* __restrict__ psq,
    const float* __restrict__ scales)
{
    constexpr int KB = DIM;              // 512 bytes per row
    constexpr int NC = KB / 128;         // 4 chunks of 128 fp8
    extern __shared__ char smem[];
    const uint32_t sbase = smem_u32(smem);

    const int tid = threadIdx.x;
    const int lane = tid & 31, wid = tid >> 5;
    const int warpM = wid >> 1, warpN = wid & 1;
    const int m0 = blockIdx.x * 128;
    const int n0 = blockIdx.y * 128;

    auto prefetch = [&](int kc) {
        const uint8_t* Ab = g_x8 + (size_t)m0 * KB + kc * 128;
        const uint8_t* Bb = g_p8 + (size_t)n0 * KB + kc * 128;
        uint32_t da = sbase + (kc & 1) * STG;
        uint32_t db = da + 16384;
        #pragma unroll
        for (int it = 0; it < 4; it++) {          // A: 128 rows x 8 16B chunks
            int i = tid + it * 256;
            int r = i >> 3, ch = i & 7;
            CP_ASYNC16(da + sw_off(r, ch * 8), Ab + (size_t)r * KB + ch * 16);
        }
        #pragma unroll
        for (int it = 0; it < 4; it++) {          // B: 128 rows x 8 16B chunks
            int i = tid + it * 256;
            int r = i >> 3, ch = i & 7;
            CP_ASYNC16(db + sw_off(r, ch * 8), Bb + (size_t)r * KB + ch * 16);
        }
        CP_COMMIT();
    };

    float acc[2][8][4];
    #pragma unroll
    for (int i = 0; i < 2; i++)
        #pragma unroll
        for (int j = 0; j < 8; j++)
            #pragma unroll
            for (int k = 0; k < 4; k++) acc[i][j][k] = 0.f;

    prefetch(0);

    for (int c = 0; c < NC; c++) {
        CP_WAIT(0);
        __syncthreads();
        if (c + 1 < NC) prefetch(c + 1);

        uint32_t sa = sbase + (c & 1) * STG;
        uint32_t sb = sa + 16384;

        #pragma unroll
        for (int ks = 0; ks < 4; ks++) {          // 4 x k32 fp8 steps
            uint32_t af[2][4], bfr[8][2];
            #pragma unroll
            for (int mi = 0; mi < 2; mi++) {
                int r = warpM * 32 + mi * 16 + (lane & 15);
                int cc = ks * 16 + ((lane >> 4) << 3);   // b16 cols
                ldsm_x4(af[mi], sa + sw_off(r, cc));
            }
            #pragma unroll
            for (int nb = 0; nb < 4; nb++) {
                int r = warpN * 64 + nb * 16 + ((lane >> 4) << 3) + (lane & 7);
                int cc = ks * 16 + (((lane >> 3) & 1) << 3);
                uint32_t f[4];
                ldsm_x4(f, sb + sw_off(r, cc));
                bfr[2 * nb][0] = f[0]; bfr[2 * nb][1] = f[1];
                bfr[2 * nb + 1][0] = f[2]; bfr[2 * nb + 1][1] = f[3];
            }
            #pragma unroll
            for (int mi = 0; mi < 2; mi++)
                #pragma unroll
                for (int nj = 0; nj < 8; nj++)
                    mma16832_e4m3(acc[mi][nj], af[mi], bfr[nj]);
        }
    }
    __syncthreads();

    // ---- epilogue ----
    const int rb = lane >> 2;
    const int cb = (lane & 3) * 2;
    float* rs_sm = reinterpret_cast<float*>(smem + SM_RS);

    #pragma unroll
    for (int mi = 0; mi < 2; mi++) {
        int rt0 = warpM * 32 + mi * 16 + rb;
        int r0 = m0 + rt0;
        float rs0 = 0.f, rs1 = 0.f;
        float xs0 = xsq[r0], xs1 = xsq[r0 + 8];
        #pragma unroll
        for (int nj = 0; nj < 8; nj++) {
            int c0 = n0 + warpN * 64 + nj * 8 + cb;
            float* a = acc[mi][nj];
            float pq0 = psq[c0], pq1 = psq[c0 + 1];
            float sc0 = scales[c0], sc1 = scales[c0 + 1];
            // S' = 16*S  ->  dist2 = xs + pq - 2S = xs + pq - 0.125*S'
            float d00 = sqrtf(fmaxf(xs0 + pq0 - 0.125f * a[0], 0.f));
            float d01 = sqrtf(fmaxf(xs0 + pq1 - 0.125f * a[1], 0.f));
            float d10 = sqrtf(fmaxf(xs1 + pq0 - 0.125f * a[2], 0.f));
            float d11 = sqrtf(fmaxf(xs1 + pq1 - 0.125f * a[3], 0.f));
            float e00 = __expf(sc0 / (d00 + 0.1f));
            float e01 = __expf(sc1 / (d01 + 0.1f));
            float e10 = __expf(sc0 / (d10 + 0.1f));
            float e11 = __expf(sc1 / (d11 + 0.1f));
            rs0 += e00 + e01;
            rs1 += e10 + e11;
            *reinterpret_cast<__half2*>(g_E + (size_t)r0 * NNEU + c0) =
                __floats2half2_rn(e00, e01);
            *reinterpret_cast<__half2*>(g_E + (size_t)(r0 + 8) * NNEU + c0) =
                __floats2half2_rn(e10, e11);
        }
        rs0 += __shfl_xor_sync(0xffffffffu, rs0, 1);
        rs0 += __shfl_xor_sync(0xffffffffu, rs0, 2);
        rs1 += __shfl_xor_sync(0xffffffffu, rs1, 1);
        rs1 += __shfl_xor_sync(0xffffffffu, rs1, 2);
        if ((lane & 3) == 0) {
            rs_sm[rt0 * 2 + warpN] = rs0;
            rs_sm[(rt0 + 8) * 2 + warpN] = rs1;
        }
    }
    __syncthreads();
    if (tid < 128) {
        float2 v = reinterpret_cast<const float2*>(rs_sm)[tid];
        g_rsp[(size_t)(m0 + tid) * 8 + blockIdx.y] = v.x + v.y;
    }
}

// ============================================================================
// f16 GEMM (R11 core): C = A @ B^T, CTA 128x128, warps 4x2 (32x64), f16 acc,
// 2-stage, 1 sync/chunk, 3 CTAs/SM.
// MODE 0: f16 store (VWt)   MODE 2: out = acc/rowsum(8 partials) + b, fp32
// ============================================================================
template<int KTOT, int MODE>
__global__ void __launch_bounds__(256, 3) k_gemm(
    const __half* __restrict__ Ag,
    const __half* __restrict__ Bg,
    void* __restrict__ dst,
    const float* __restrict__ aux0,   // rsp partials (M2)
    const float* __restrict__ aux1)   // bout (M2)
{
    constexpr int NC = KTOT / 64;
    extern __shared__ char smem[];
    const uint32_t sbase = smem_u32(smem);

    const int tid = threadIdx.x;
    const int lane = tid & 31, wid = tid >> 5;
    const int warpM = wid >> 1, warpN = wid & 1;
    const int m0 = blockIdx.x * 128;
    const int n0 = blockIdx.y * 128;

    auto prefetch = [&](int kc) {
        const __half* Ab = Ag + (size_t)m0 * KTOT + kc * 64;
        const __half* Bb = Bg + (size_t)n0 * KTOT + kc * 64;
        uint32_t da = sbase + (kc & 1) * STG;
        uint32_t db = da + 16384;
        #pragma unroll
        for (int it = 0; it < 4; it++) {
            int i = tid + it * 256;
            int r = i >> 3, ch = i & 7;
            CP_ASYNC16(da + sw_off(r, ch * 8), Ab + (size_t)r * KTOT + ch * 8);
        }
        #pragma unroll
        for (int it = 0; it < 4; it++) {
            int i = tid + it * 256;
            int r = i >> 3, ch = i & 7;
            CP_ASYNC16(db + sw_off(r, ch * 8), Bb + (size_t)r * KTOT + ch * 8);
        }
        CP_COMMIT();
    };

    uint32_t acc[2][8][2];
    #pragma unroll
    for (int i = 0; i < 2; i++)
        #pragma unroll
        for (int j = 0; j < 8; j++) { acc[i][j][0] = 0u; acc[i][j][1] = 0u; }

    prefetch(0);

    for (int c = 0; c < NC; c++) {
        CP_WAIT(0);
        __syncthreads();
        if (c + 1 < NC) prefetch(c + 1);

        uint32_t sa = sbase + (c & 1) * STG;
        uint32_t sb = sa + 16384;

        #pragma unroll
        for (int ks = 0; ks < 4; ks++) {
            uint32_t af[2][4], bfr[8][2];
            #pragma unroll
            for (int mi = 0; mi < 2; mi++) {
                int r = warpM * 32 + mi * 16 + (lane & 15);
                int cc = ks * 16 + ((lane >> 4) << 3);
                ldsm_x4(af[mi], sa + sw_off(r, cc));
            }
            #pragma unroll
            for (int nb = 0; nb < 4; nb++) {
                int r = warpN * 64 + nb * 16 + ((lane >> 4) << 3) + (lane & 7);
                int cc = ks * 16 + (((lane >> 3) & 1) << 3);
                uint32_t f[4];
                ldsm_x4(f, sb + sw_off(r, cc));
                bfr[2 * nb][0] = f[0]; bfr[2 * nb][1] = f[1];
                bfr[2 * nb + 1][0] = f[2]; bfr[2 * nb + 1][1] = f[3];
            }
            #pragma unroll
            for (int mi = 0; mi < 2; mi++)
                #pragma unroll
                for (int nj = 0; nj < 8; nj++)
                    mma16816_f16(acc[mi][nj], af[mi], bfr[nj]);
        }
    }
    __syncthreads();

    // ---- epilogue ----
    const int rb = lane >> 2;
    const int cb = (lane & 3) * 2;

    #pragma unroll
    for (int mi = 0; mi < 2; mi++) {
        int rt0 = warpM * 32 + mi * 16 + rb;
        int r0 = m0 + rt0;
        float iv0 = 0.f, iv1 = 0.f;
        if (MODE == 2) {
            float4 a0 = *reinterpret_cast<const float4*>(aux0 + (size_t)r0 * 8);
            float4 a1 = *reinterpret_cast<const float4*>(aux0 + (size_t)r0 * 8 + 4);
            float4 b0 = *reinterpret_cast<const float4*>(aux0 + (size_t)(r0 + 8) * 8);
            float4 b1 = *reinterpret_cast<const float4*>(aux0 + (size_t)(r0 + 8) * 8 + 4);
            iv0 = 1.f / ((a0.x + a0.y + a0.z + a0.w) + (a1.x + a1.y + a1.z + a1.w));
            iv1 = 1.f / ((b0.x + b0.y + b0.z + b0.w) + (b1.x + b1.y + b1.z + b1.w));
        }
        #pragma unroll
        for (int nj = 0; nj < 8; nj++) {
            int c0 = n0 + warpN * 64 + nj * 8 + cb;
            __half2 h0 = *reinterpret_cast<__half2*>(&acc[mi][nj][0]);
            __half2 h1 = *reinterpret_cast<__half2*>(&acc[mi][nj][1]);
            if (MODE == 0) {
                __half* D = (__half*)dst;
                *reinterpret_cast<__half2*>(D + (size_t)r0 * NNEU + c0) = h0;
                *reinterpret_cast<__half2*>(D + (size_t)(r0 + 8) * NNEU + c0) = h1;
            } else {
                float* D = (float*)dst;
                float2 f0 = __half22float2(h0);
                float2 f1 = __half22float2(h1);
                float b0 = aux1[c0], b1 = aux1[c0 + 1];
                float2 o0 = make_float2(f0.x * iv0 + b0, f0.y * iv0 + b1);
                float2 o1 = make_float2(f1.x * iv1 + b0, f1.y * iv1 + b1);
                *reinterpret_cast<float2*>(D + (size_t)r0 * DIM + c0) = o0;
                *reinterpret_cast<float2*>(D + (size_t)(r0 + 8) * DIM + c0) = o1;
            }
        }
    }
}

// ============================================================================
// Host launcher — fork/join second stream for conv+VWt overlap with
// rowsq+scores. Stream/events created on first (uncaptured) call only.
// ============================================================================
extern "C" void kernel_launch(void* const* d_in, const int* in_sizes, int n_in,
                              void* d_out, int out_size) {
    (void)in_sizes; (void)n_in; (void)out_size;
    const float* x      = (const float*)d_in[0];
    const float* pos    = (const float*)d_in[1];
    const float* scales = (const float*)d_in[2];
    const float* values = (const float*)d_in[3];
    const float* W      = (const float*)d_in[4];
    const float* b      = (const float*)d_in[5];
    float* out = (float*)d_out;

    static __half* vwt_p = nullptr;
    static __half* E_p   = nullptr;
    static float *xsq_p, *psq_p, *rsp_p;
    static __half *vb_p, *wb_p;
    static cudaStream_t s2;
    static cudaEvent_t eFork, eJoin;
    if (!vwt_p) {
        cudaGetSymbolAddress((void**)&vwt_p, g_vwt);
        cudaGetSymbolAddress((void**)&E_p,   g_E);
        cudaGetSymbolAddress((void**)&xsq_p, g_xsq);
        cudaGetSymbolAddress((void**)&psq_p, g_psq);
        cudaGetSymbolAddress((void**)&rsp_p, g_rsp);
        cudaGetSymbolAddress((void**)&vb_p,  g_vb);
        cudaGetSymbolAddress((void**)&wb_p,  g_wb);
        cudaStreamCreateWithFlags(&s2, cudaStreamNonBlocking);
        cudaEventCreateWithFlags(&eFork, cudaEventDisableTiming);
        cudaEventCreateWithFlags(&eJoin, cudaEventDisableTiming);
        cudaFuncSetAttribute(k_scores8,
            cudaFuncAttributeMaxDynamicSharedMemorySize, SMEM_SZ);
        cudaFuncSetAttribute(k_gemm<512, 0>,
            cudaFuncAttributeMaxDynamicSharedMemorySize, SMEM_SZ);
        cudaFuncSetAttribute(k_gemm<1024, 2>,
            cudaFuncAttributeMaxDynamicSharedMemorySize, SMEM_SZ);
    }

    // fork side stream: conv -> VWt GEMM (independent of x path)
    cudaEventRecord(eFork, 0);
    cudaStreamWaitEvent(s2, eFork, 0);
    k_conv<<<((NNEU * DIM + DIM * DIM) / 4) / 256, 256, 0, s2>>>(values, W);
    k_gemm<512, 0><<<dim3(4, 8), 256, SMEM_SZ, s2>>>(
        wb_p, vb_p, vwt_p, nullptr, nullptr);
    cudaEventRecord(eJoin, s2);

    // main stream: rowsq (fp8 convert) -> fp8 score GEMM
    k_rowsq<<<(MTOT + NNEU) / 8, 256>>>(x, pos);
    k_scores8<<<dim3(128, 8), 256, SMEM_SZ>>>(xsq_p, psq_p, scales);

    // join, then out = E @ VWt^T / rowsum + b   (rowsum inlined from g_rsp)
    cudaStreamWaitEvent(0, eJoin, 0);
    k_gemm<1024, 2><<<dim3(128, 4), 256, SMEM_SZ>>>(
        E_p, vwt_p, out, rsp_p, b);
}

// round 13
// speedup vs baseline: 1.0460x; 1.0460x over previous
#include <cuda_runtime.h>
#include <cuda_fp16.h>
#include <cstdint>

// ============================================================================
// CrystalAttention, sm_100-baseline ISA (mma.sync + cp.async; no tcgen05).
//   VWt[d][n] = sum_k W[d,k] V[n,k]
//   S = X @ P^T ; E = exp(scales/(sqrt(max(xsq+psq-2S,0))+0.1))
//   out = (E @ VWt^T) / rowsum(E) + b_out
// M=16384, D=512, N=1024.
// R13: fp16 f16-accum core (R11), but K-chunk 32 with a 4-stage cp.async
// pipeline (3 chunks in flight) at unchanged smem/CTA -> 3 CTAs/SM.
// Stage rows are 64B pitch with SW64-style swizzle.
// ============================================================================
#define MTOT 16384
#define DIM  512
#define NNEU 1024

__device__ __half  g_xb[(size_t)MTOT * DIM];
__device__ float   g_xsq[MTOT];
__device__ __half  g_pb[(size_t)NNEU * DIM];
__device__ float   g_psq[NNEU];
__device__ __half  g_vb[(size_t)NNEU * DIM];
__device__ __half  g_wb[(size_t)DIM * DIM];
__device__ __half  g_vwt[(size_t)DIM * NNEU];
__device__ __half  g_E[(size_t)MTOT * NNEU];
__device__ float   g_rsp[(size_t)MTOT * 8];   // partial rowsums per nb

// ============================================================================
// helpers
// ============================================================================
__device__ __forceinline__ uint32_t smem_u32(const void* p) {
    uint32_t a;
    asm("{ .reg .u64 t; cvta.to.shared.u64 t, %1; cvt.u32.u64 %0, t; }"
        : "=r"(a) : "l"(p));
    return a;
}

#define CP_ASYNC16(saddr, gaddr) \
    asm volatile("cp.async.cg.shared.global [%0], [%1], 16;\n" \
                 :: "r"(saddr), "l"(gaddr) : "memory")
#define CP_COMMIT() asm volatile("cp.async.commit_group;\n" ::: "memory")
#define CP_WAIT(n)  asm volatile("cp.async.wait_group %0;\n" :: "n"(n) : "memory")

__device__ __forceinline__ void ldsm_x4(uint32_t* f, uint32_t addr) {
    asm volatile("ldmatrix.sync.aligned.m8n8.x4.shared.b16 {%0,%1,%2,%3}, [%4];\n"
                 : "=r"(f[0]), "=r"(f[1]), "=r"(f[2]), "=r"(f[3]) : "r"(addr));
}

// f16-accumulate MMA: D(f16x2 x2) = A(f16 x4) * B(f16 x2) + D
__device__ __forceinline__ void mma16816_f16(uint32_t* d, const uint32_t* a,
                                             const uint32_t* b) {
    asm volatile(
        "mma.sync.aligned.m16n8k16.row.col.f16.f16.f16.f16 "
        "{%0,%1}, {%2,%3,%4,%5}, {%6,%7}, {%0,%1};\n"
        : "+r"(d[0]), "+r"(d[1])
        : "r"(a[0]), "r"(a[1]), "r"(a[2]), "r"(a[3]), "r"(b[0]), "r"(b[1]));
}

// 64B-pitch stage: row r, b16 col c (c%8==0, c<32).
// slot bits[5:4] ^= (r>>1)&3  -> conflict-free for 8-row ldmatrix.
__device__ __forceinline__ uint32_t sw64_off(int r, int c) {
    return (uint32_t)(r * 64 + ((((c >> 3) ^ ((r >> 1) & 3))) << 4));
}

// ============================================================================
// prep: fp32->fp16 + row sum-of-squares. One warp per row, 4 float4 per lane.
// ============================================================================
__global__ void k_rowsq(const float* __restrict__ x, const float* __restrict__ pos) {
    int gw = blockIdx.x * 8 + (threadIdx.x >> 5);
    int lane = threadIdx.x & 31;
    const float* src;
    __half* dstB;
    float* dstS;
    int r;
    if (gw < MTOT) { src = x;   dstB = g_xb; dstS = g_xsq; r = gw; }
    else           { src = pos; dstB = g_pb; dstS = g_psq; r = gw - MTOT; }

    const float4* p = reinterpret_cast<const float4*>(src) + (size_t)r * (DIM / 4);
    uint2* q = reinterpret_cast<uint2*>(dstB) + (size_t)r * (DIM / 4);
    float s = 0.f;
    #pragma unroll
    for (int i = 0; i < 4; i++) {
        float4 v = p[lane + 32 * i];
        __half2 p0 = __floats2half2_rn(v.x, v.y);
        __half2 p1 = __floats2half2_rn(v.z, v.w);
        uint2 u;
        u.x = *reinterpret_cast<uint32_t*>(&p0);
        u.y = *reinterpret_cast<uint32_t*>(&p1);
        q[lane + 32 * i] = u;
        s += v.x * v.x + v.y * v.y + v.z * v.z + v.w * v.w;
    }
    #pragma unroll
    for (int off = 16; off > 0; off >>= 1)
        s += __shfl_xor_sync(0xffffffffu, s, off);
    if (lane == 0) dstS[r] = s;
}

// prep: fp32->fp16 for values then W_out, one grid
__global__ void k_conv(const float* __restrict__ values, const float* __restrict__ W) {
    constexpr int NV4 = (NNEU * DIM) / 4;   // 131072
    int i = blockIdx.x * blockDim.x + threadIdx.x;
    const float* src;
    __half* dst;
    int j;
    if (i < NV4) { src = values; dst = g_vb; j = i; }
    else         { src = W;      dst = g_wb; j = i - NV4; }
    float4 v = reinterpret_cast<const float4*>(src)[j];
    __half2 p0 = __floats2half2_rn(v.x, v.y);
    __half2 p1 = __floats2half2_rn(v.z, v.w);
    uint2 u;
    u.x = *reinterpret_cast<uint32_t*>(&p0);
    u.y = *reinterpret_cast<uint32_t*>(&p1);
    reinterpret_cast<uint2*>(dst)[j] = u;
}

// ============================================================================
// GEMM: C = A @ B^T. CTA tile 128(M) x 128(N), K chunk 32, 4-stage cp.async
// (3 chunks in flight), single __syncthreads per chunk. 256 threads:
// warpM = wid>>1 (4), warpN = wid&1 (2); warp tile 32x64, f16 acc. 3 CTAs/SM.
// MODE 0: f16 store (VWt)     MODE 1: E=exp(score), f16 + partial rowsum
// MODE 2: out = acc/rowsum(8 partials inline) + b, fp32
// ============================================================================
constexpr int STG    = 16384;            // bytes per stage (A 8KB + B 8KB)
constexpr int SM_RS  = 4 * STG;          // rowsum scratch (128*2 floats)
constexpr int SMEM_SZ = SM_RS + 1024;    // 66560 B/CTA; 3 CTAs = 195 KB

template<int KTOT, int MODE>
__global__ void __launch_bounds__(256, 3) k_gemm(
    const __half* __restrict__ Ag,
    const __half* __restrict__ Bg,
    void* __restrict__ dst,
    const float* __restrict__ aux0,   // xsq (M1) / rsp partials (M2)
    const float* __restrict__ aux1,   // psq (M1) / bout  (M2)
    const float* __restrict__ aux2)   // scales (M1)
{
    constexpr int NC = KTOT / 32;        // chunks of 32 b16 cols (64 bytes)
    extern __shared__ char smem[];
    const uint32_t sbase = smem_u32(smem);

    const int tid = threadIdx.x;
    const int lane = tid & 31, wid = tid >> 5;
    const int warpM = wid >> 1, warpN = wid & 1;
    const int m0 = blockIdx.x * 128;
    const int n0 = blockIdx.y * 128;

    // 8KB per operand per stage: 512 x 16B; 2 transfers/thread/operand.
    auto prefetch = [&](int kc) {
        const __half* Ab = Ag + (size_t)m0 * KTOT + kc * 32;
        const __half* Bb = Bg + (size_t)n0 * KTOT + kc * 32;
        uint32_t da = sbase + (kc & 3) * STG;
        uint32_t db = da + 8192;
        #pragma unroll
        for (int it = 0; it < 2; it++) {          // A: 128 rows x 4 16B slots
            int i = tid + it * 256;
            int r = i >> 2, ch = i & 3;
            CP_ASYNC16(da + sw64_off(r, ch * 8), Ab + (size_t)r * KTOT + ch * 8);
        }
        #pragma unroll
        for (int it = 0; it < 2; it++) {          // B: 128 rows x 4 16B slots
            int i = tid + it * 256;
            int r = i >> 2, ch = i & 3;
            CP_ASYNC16(db + sw64_off(r, ch * 8), Bb + (size_t)r * KTOT + ch * 8);
        }
        CP_COMMIT();
    };

    uint32_t acc[2][8][2];    // f16x2 accumulators
    #pragma unroll
    for (int i = 0; i < 2; i++)
        #pragma unroll
        for (int j = 0; j < 8; j++) { acc[i][j][0] = 0u; acc[i][j][1] = 0u; }

    prefetch(0);
    prefetch(1);
    prefetch(2);

    for (int c = 0; c < NC; c++) {
        // Wait until chunk c's group is complete (outstanding groups are
        // c..min(c+2,NC-1)); then barrier (globalizes c's data AND proves
        // compute(c-1) done -> buffer (c+3)&3 == (c-1)&3 free), then refill.
        if (c + 2 < NC)      CP_WAIT(2);
        else if (c + 1 < NC) CP_WAIT(1);
        else                 CP_WAIT(0);
        __syncthreads();
        if (c + 3 < NC) prefetch(c + 3);

        uint32_t sa = sbase + (c & 3) * STG;
        uint32_t sb = sa + 8192;

        #pragma unroll
        for (int ks = 0; ks < 2; ks++) {
            uint32_t af[2][4], bfr[8][2];
            #pragma unroll
            for (int mi = 0; mi < 2; mi++) {
                int r = warpM * 32 + mi * 16 + (lane & 15);
                int cc = ks * 16 + ((lane >> 4) << 3);
                ldsm_x4(af[mi], sa + sw64_off(r, cc));
            }
            #pragma unroll
            for (int nb = 0; nb < 4; nb++) {
                int r = warpN * 64 + nb * 16 + ((lane >> 4) << 3) + (lane & 7);
                int cc = ks * 16 + (((lane >> 3) & 1) << 3);
                uint32_t f[4];
                ldsm_x4(f, sb + sw64_off(r, cc));
                bfr[2 * nb][0] = f[0]; bfr[2 * nb][1] = f[1];
                bfr[2 * nb + 1][0] = f[2]; bfr[2 * nb + 1][1] = f[3];
            }
            #pragma unroll
            for (int mi = 0; mi < 2; mi++)
                #pragma unroll
                for (int nj = 0; nj < 8; nj++)
                    mma16816_f16(acc[mi][nj], af[mi], bfr[nj]);
        }
    }
    __syncthreads();

    // ---- epilogue ----
    const int rb = lane >> 2;
    const int cb = (lane & 3) * 2;
    float* rs_sm = reinterpret_cast<float*>(smem + SM_RS);

    #pragma unroll
    for (int mi = 0; mi < 2; mi++) {
        int rt0 = warpM * 32 + mi * 16 + rb;       // row in tile; +8 for second
        int r0 = m0 + rt0;
        float rs0 = 0.f, rs1 = 0.f;
        float iv0 = 0.f, iv1 = 0.f;
        if (MODE == 2) {
            // inline rowsum: 8 partials per row
            float4 a0 = *reinterpret_cast<const float4*>(aux0 + (size_t)r0 * 8);
            float4 a1 = *reinterpret_cast<const float4*>(aux0 + (size_t)r0 * 8 + 4);
            float4 b0 = *reinterpret_cast<const float4*>(aux0 + (size_t)(r0 + 8) * 8);
            float4 b1 = *reinterpret_cast<const float4*>(aux0 + (size_t)(r0 + 8) * 8 + 4);
            iv0 = 1.f / ((a0.x + a0.y + a0.z + a0.w) + (a1.x + a1.y + a1.z + a1.w));
            iv1 = 1.f / ((b0.x + b0.y + b0.z + b0.w) + (b1.x + b1.y + b1.z + b1.w));
        }
        #pragma unroll
        for (int nj = 0; nj < 8; nj++) {
            int c0 = n0 + warpN * 64 + nj * 8 + cb;
            __half2 h0 = *reinterpret_cast<__half2*>(&acc[mi][nj][0]); // row r0
            __half2 h1 = *reinterpret_cast<__half2*>(&acc[mi][nj][1]); // row r0+8
            if (MODE == 0) {
                __half* D = (__half*)dst;
                *reinterpret_cast<__half2*>(D + (size_t)r0 * NNEU + c0) = h0;
                *reinterpret_cast<__half2*>(D + (size_t)(r0 + 8) * NNEU + c0) = h1;
            } else if (MODE == 1) {
                __half* D = (__half*)dst;
                float2 f0 = __half22float2(h0);
                float2 f1 = __half22float2(h1);
                float xs0 = aux0[r0], xs1 = aux0[r0 + 8];
                float pq0 = aux1[c0], pq1 = aux1[c0 + 1];
                float sc0 = aux2[c0], sc1 = aux2[c0 + 1];
                float d00 = sqrtf(fmaxf(xs0 + pq0 - 2.f * f0.x, 0.f));
                float d01 = sqrtf(fmaxf(xs0 + pq1 - 2.f * f0.y, 0.f));
                float d10 = sqrtf(fmaxf(xs1 + pq0 - 2.f * f1.x, 0.f));
                float d11 = sqrtf(fmaxf(xs1 + pq1 - 2.f * f1.y, 0.f));
                float e00 = __expf(sc0 / (d00 + 0.1f));
                float e01 = __expf(sc1 / (d01 + 0.1f));
                float e10 = __expf(sc0 / (d10 + 0.1f));
                float e11 = __expf(sc1 / (d11 + 0.1f));
                rs0 += e00 + e01;
                rs1 += e10 + e11;
                *reinterpret_cast<__half2*>(D + (size_t)r0 * NNEU + c0) =
                    __floats2half2_rn(e00, e01);
                *reinterpret_cast<__half2*>(D + (size_t)(r0 + 8) * NNEU + c0) =
                    __floats2half2_rn(e10, e11);
            } else {
                float* D = (float*)dst;
                float2 f0 = __half22float2(h0);
                float2 f1 = __half22float2(h1);
                float b0 = aux1[c0], b1 = aux1[c0 + 1];
                float2 o0 = make_float2(f0.x * iv0 + b0, f0.y * iv0 + b1);
                float2 o1 = make_float2(f1.x * iv1 + b0, f1.y * iv1 + b1);
                *reinterpret_cast<float2*>(D + (size_t)r0 * DIM + c0) = o0;
                *reinterpret_cast<float2*>(D + (size_t)(r0 + 8) * DIM + c0) = o1;
            }
        }
        if (MODE == 1) {
            // reduce over the 4 lanes of the quad (cols), leave on lane&3==0
            rs0 += __shfl_xor_sync(0xffffffffu, rs0, 1);
            rs0 += __shfl_xor_sync(0xffffffffu, rs0, 2);
            rs1 += __shfl_xor_sync(0xffffffffu, rs1, 1);
            rs1 += __shfl_xor_sync(0xffffffffu, rs1, 2);
            if ((lane & 3) == 0) {
                rs_sm[rt0 * 2 + warpN] = rs0;
                rs_sm[(rt0 + 8) * 2 + warpN] = rs1;
            }
        }
    }
    if (MODE == 1) {
        __syncthreads();
        if (tid < 128) {
            float2 v = reinterpret_cast<const float2*>(rs_sm)[tid];
            g_rsp[(size_t)(m0 + tid) * 8 + blockIdx.y] = v.x + v.y;
        }
    }
}

// ============================================================================
// Host launcher — fork/join second stream for conv+VWt overlap with
// rowsq+scores. Stream/events created on first (uncaptured) call only.
// ============================================================================
extern "C" void kernel_launch(void* const* d_in, const int* in_sizes, int n_in,
                              void* d_out, int out_size) {
    (void)in_sizes; (void)n_in; (void)out_size;
    const float* x      = (const float*)d_in[0];
    const float* pos    = (const float*)d_in[1];
    const float* scales = (const float*)d_in[2];
    const float* values = (const float*)d_in[3];
    const float* W      = (const float*)d_in[4];
    const float* b      = (const float*)d_in[5];
    float* out = (float*)d_out;

    static __half* vwt_p = nullptr;
    static __half* E_p   = nullptr;
    static float *xsq_p, *psq_p, *rsp_p;
    static __half *xb_p, *pb_p, *vb_p, *wb_p;
    static cudaStream_t s2;
    static cudaEvent_t eFork, eJoin;
    if (!vwt_p) {
        cudaGetSymbolAddress((void**)&vwt_p, g_vwt);
        cudaGetSymbolAddress((void**)&E_p,   g_E);
        cudaGetSymbolAddress((void**)&xsq_p, g_xsq);
        cudaGetSymbolAddress((void**)&psq_p, g_psq);
        cudaGetSymbolAddress((void**)&rsp_p, g_rsp);
        cudaGetSymbolAddress((void**)&xb_p,  g_xb);
        cudaGetSymbolAddress((void**)&pb_p,  g_pb);
        cudaGetSymbolAddress((void**)&vb_p,  g_vb);
        cudaGetSymbolAddress((void**)&wb_p,  g_wb);
        cudaStreamCreateWithFlags(&s2, cudaStreamNonBlocking);
        cudaEventCreateWithFlags(&eFork, cudaEventDisableTiming);
        cudaEventCreateWithFlags(&eJoin, cudaEventDisableTiming);
        cudaFuncSetAttribute(k_gemm<512, 0>,
            cudaFuncAttributeMaxDynamicSharedMemorySize, SMEM_SZ);
        cudaFuncSetAttribute(k_gemm<512, 1>,
            cudaFuncAttributeMaxDynamicSharedMemorySize, SMEM_SZ);
        cudaFuncSetAttribute(k_gemm<1024, 2>,
            cudaFuncAttributeMaxDynamicSharedMemorySize, SMEM_SZ);
    }

    // fork side stream: conv -> VWt GEMM (independent of x path)
    cudaEventRecord(eFork, 0);
    cudaStreamWaitEvent(s2, eFork, 0);
    k_conv<<<((NNEU * DIM + DIM * DIM) / 4) / 256, 256, 0, s2>>>(values, W);
    k_gemm<512, 0><<<dim3(4, 8), 256, SMEM_SZ, s2>>>(
        wb_p, vb_p, vwt_p, nullptr, nullptr, nullptr);
    cudaEventRecord(eJoin, s2);

    // main stream: rowsq -> scores
    k_rowsq<<<(MTOT + NNEU) / 8, 256>>>(x, pos);
    k_gemm<512, 1><<<dim3(128, 8), 256, SMEM_SZ>>>(
        xb_p, pb_p, E_p, xsq_p, psq_p, scales);

    // join, then out = E @ VWt^T / rowsum + b   (rowsum inlined from g_rsp)
    cudaStreamWaitEvent(0, eJoin, 0);
    k_gemm<1024, 2><<<dim3(128, 4), 256, SMEM_SZ>>>(
        E_p, vwt_p, out, rsp_p, b, nullptr);
}

// round 15
// speedup vs baseline: 1.0499x; 1.0037x over previous
#include <cuda_runtime.h>
#include <cuda_fp16.h>
#include <cstdint>

// ============================================================================
// CrystalAttention, sm_100-baseline ISA (mma.sync + cp.async; no tcgen05).
//   VWt[d][n] = sum_k W[d,k] V[n,k]
//   S = X @ P^T ; E = exp(scales/(sqrt(max(xsq+psq-2S,0))+0.1))
//   out = (E @ VWt^T) / rowsum(E) + b_out
// M=16384, D=512, N=1024.
// R14: fp16 f16-accum core, CTA tile 128x256, warp tile 64x64 (2x4 warps),
// 2-stage cp.async K-chunk 64, 1 sync/chunk, 2 CTAs/SM. Target: cut smem
// ldsm traffic per FLOP (crossbar-bound per R11 model).
// ============================================================================
#define MTOT 16384
#define DIM  512
#define NNEU 1024

__device__ __half  g_xb[(size_t)MTOT * DIM];
__device__ float   g_xsq[MTOT];
__device__ __half  g_pb[(size_t)NNEU * DIM];
__device__ float   g_psq[NNEU];
__device__ __half  g_vb[(size_t)NNEU * DIM];
__device__ __half  g_wb[(size_t)DIM * DIM];
__device__ __half  g_vwt[(size_t)DIM * NNEU];
__device__ __half  g_E[(size_t)MTOT * NNEU];
__device__ float   g_rsp[(size_t)MTOT * 4];   // partial rowsums per nb

// ============================================================================
// helpers
// ============================================================================
__device__ __forceinline__ uint32_t smem_u32(const void* p) {
    uint32_t a;
    asm("{ .reg .u64 t; cvta.to.shared.u64 t, %1; cvt.u32.u64 %0, t; }"
        : "=r"(a) : "l"(p));
    return a;
}

#define CP_ASYNC16(saddr, gaddr) \
    asm volatile("cp.async.cg.shared.global [%0], [%1], 16;\n" \
                 :: "r"(saddr), "l"(gaddr) : "memory")
#define CP_COMMIT() asm volatile("cp.async.commit_group;\n" ::: "memory")
#define CP_WAIT(n)  asm volatile("cp.async.wait_group %0;\n" :: "n"(n) : "memory")

__device__ __forceinline__ void ldsm_x4(uint32_t* f, uint32_t addr) {
    asm volatile("ldmatrix.sync.aligned.m8n8.x4.shared.b16 {%0,%1,%2,%3}, [%4];\n"
                 : "=r"(f[0]), "=r"(f[1]), "=r"(f[2]), "=r"(f[3]) : "r"(addr));
}

// f16-accumulate MMA: D(f16x2 x2) = A(f16 x4) * B(f16 x2) + D
__device__ __forceinline__ void mma16816_f16(uint32_t* d, const uint32_t* a,
                                             const uint32_t* b) {
    asm volatile(
        "mma.sync.aligned.m16n8k16.row.col.f16.f16.f16.f16 "
        "{%0,%1}, {%2,%3,%4,%5}, {%6,%7}, {%0,%1};\n"
        : "+r"(d[0]), "+r"(d[1])
        : "r"(a[0]), "r"(a[1]), "r"(a[2]), "r"(a[3]), "r"(b[0]), "r"(b[1]));
}

// swizzled smem byte offset, 128B pitch rows, b16 col c (c%8==0)
__device__ __forceinline__ uint32_t sw_off(int r, int c) {
    return (uint32_t)(r * 128 + ((((c >> 3) ^ (r & 7))) << 4));
}

// ============================================================================
// prep: fp32->fp16 + row sum-of-squares. One warp per row, 4 float4 per lane.
// ============================================================================
__global__ void k_rowsq(const float* __restrict__ x, const float* __restrict__ pos) {
    int gw = blockIdx.x * 8 + (threadIdx.x >> 5);
    int lane = threadIdx.x & 31;
    const float* src;
    __half* dstB;
    float* dstS;
    int r;
    if (gw < MTOT) { src = x;   dstB = g_xb; dstS = g_xsq; r = gw; }
    else           { src = pos; dstB = g_pb; dstS = g_psq; r = gw - MTOT; }

    const float4* p = reinterpret_cast<const float4*>(src) + (size_t)r * (DIM / 4);
    uint2* q = reinterpret_cast<uint2*>(dstB) + (size_t)r * (DIM / 4);
    float s = 0.f;
    #pragma unroll
    for (int i = 0; i < 4; i++) {
        float4 v = p[lane + 32 * i];
        __half2 p0 = __floats2half2_rn(v.x, v.y);
        __half2 p1 = __floats2half2_rn(v.z, v.w);
        uint2 u;
        u.x = *reinterpret_cast<uint32_t*>(&p0);
        u.y = *reinterpret_cast<uint32_t*>(&p1);
        q[lane + 32 * i] = u;
        s += v.x * v.x + v.y * v.y + v.z * v.z + v.w * v.w;
    }
    #pragma unroll
    for (int off = 16; off > 0; off >>= 1)
        s += __shfl_xor_sync(0xffffffffu, s, off);
    if (lane == 0) dstS[r] = s;
}

// prep: fp32->fp16 for values then W_out, one grid
__global__ void k_conv(const float* __restrict__ values, const float* __restrict__ W) {
    constexpr int NV4 = (NNEU * DIM) / 4;   // 131072
    int i = blockIdx.x * blockDim.x + threadIdx.x;
    const float* src;
    __half* dst;
    int j;
    if (i < NV4) { src = values; dst = g_vb; j = i; }
    else         { src = W;      dst = g_wb; j = i - NV4; }
    float4 v = reinterpret_cast<const float4*>(src)[j];
    __half2 p0 = __floats2half2_rn(v.x, v.y);
    __half2 p1 = __floats2half2_rn(v.z, v.w);
    uint2 u;
    u.x = *reinterpret_cast<uint32_t*>(&p0);
    u.y = *reinterpret_cast<uint32_t*>(&p1);
    reinterpret_cast<uint2*>(dst)[j] = u;
}

// ============================================================================
// GEMM: C = A @ B^T. CTA tile 128(M) x 256(N), K chunk 64, 2-stage cp.async,
// single __syncthreads per chunk (wait -> barrier -> prefetch -> compute).
// 256 threads: warpM = wid>>2 (2), warpN = wid&3 (4); warp tile 64x64,
// f16 accumulators (64 regs). 2 CTAs/SM.
// MODE 0: f16 store (VWt)     MODE 1: E=exp(score), f16 + partial rowsum
// MODE 2: out = acc/rowsum(4 partials inline) + b, fp32
// ============================================================================
constexpr int STG    = 49152;            // bytes per stage (A 16KB + B 32KB)
constexpr int SM_RS  = 2 * STG;          // rowsum scratch (128*4 floats)
constexpr int SMEM_SZ = SM_RS + 2048;    // 100352 B/CTA; 2 CTAs = 196 KB

template<int KTOT, int MODE>
__global__ void __launch_bounds__(256, 2) k_gemm(
    const __half* __restrict__ Ag,
    const __half* __restrict__ Bg,
    void* __restrict__ dst,
    const float* __restrict__ aux0,   // xsq (M1) / rsp partials (M2)
    const float* __restrict__ aux1,   // psq (M1) / bout  (M2)
    const float* __restrict__ aux2)   // scales (M1)
{
    constexpr int NC = KTOT / 64;
    extern __shared__ char smem[];
    const uint32_t sbase = smem_u32(smem);

    const int tid = threadIdx.x;
    const int lane = tid & 31, wid = tid >> 5;
    const int warpM = wid >> 2, warpN = wid & 3;
    const int m0 = blockIdx.x * 128;
    const int n0 = blockIdx.y * 256;

    auto prefetch = [&](int kc) {
        const __half* Ab = Ag + (size_t)m0 * KTOT + kc * 64;
        const __half* Bb = Bg + (size_t)n0 * KTOT + kc * 64;
        uint32_t da = sbase + (kc & 1) * STG;
        uint32_t db = da + 16384;
        #pragma unroll
        for (int it = 0; it < 4; it++) {          // A: 128 rows x 8 chunks
            int i = tid + it * 256;
            int r = i >> 3, ch = i & 7;
            CP_ASYNC16(da + sw_off(r, ch * 8), Ab + (size_t)r * KTOT + ch * 8);
        }
        #pragma unroll
        for (int it = 0; it < 8; it++) {          // B: 256 rows x 8 chunks
            int i = tid + it * 256;
            int r = i >> 3, ch = i & 7;
            CP_ASYNC16(db + sw_off(r, ch * 8), Bb + (size_t)r * KTOT + ch * 8);
        }
        CP_COMMIT();
    };

    uint32_t acc[4][8][2];    // f16x2 accumulators (64 regs)
    #pragma unroll
    for (int i = 0; i < 4; i++)
        #pragma unroll
        for (int j = 0; j < 8; j++) { acc[i][j][0] = 0u; acc[i][j][1] = 0u; }

    prefetch(0);

    for (int c = 0; c < NC; c++) {
        // Wait for own copies of chunk c, then barrier: makes all threads'
        // chunk-c data globally visible AND proves all warps finished
        // compute(c-1) -> buffer (c+1)&1 == (c-1)&1 is free for prefetch.
        CP_WAIT(0);
        __syncthreads();
        if (c + 1 < NC) prefetch(c + 1);

        uint32_t sa = sbase + (c & 1) * STG;
        uint32_t sb = sa + 16384;

        #pragma unroll
        for (int ks = 0; ks < 4; ks++) {
            uint32_t af[4][4], bfr[8][2];
            #pragma unroll
            for (int mi = 0; mi < 4; mi++) {
                int r = warpM * 64 + mi * 16 + (lane & 15);
                int cc = ks * 16 + ((lane >> 4) << 3);
                ldsm_x4(af[mi], sa + sw_off(r, cc));
            }
            #pragma unroll
            for (int nb = 0; nb < 4; nb++) {
                int r = warpN * 64 + nb * 16 + ((lane >> 4) << 3) + (lane & 7);
                int cc = ks * 16 + (((lane >> 3) & 1) << 3);
                uint32_t f[4];
                ldsm_x4(f, sb + sw_off(r, cc));
                bfr[2 * nb][0] = f[0]; bfr[2 * nb][1] = f[1];
                bfr[2 * nb + 1][0] = f[2]; bfr[2 * nb + 1][1] = f[3];
            }
            #pragma unroll
            for (int mi = 0; mi < 4; mi++)
                #pragma unroll
                for (int nj = 0; nj < 8; nj++)
                    mma16816_f16(acc[mi][nj], af[mi], bfr[nj]);
        }
    }
    __syncthreads();

    // ---- epilogue ----
    const int rb = lane >> 2;
    const int cb = (lane & 3) * 2;
    float* rs_sm = reinterpret_cast<float*>(smem + SM_RS);

    #pragma unroll
    for (int mi = 0; mi < 4; mi++) {
        int rt0 = warpM * 64 + mi * 16 + rb;       // row in tile; +8 for second
        int r0 = m0 + rt0;
        float rs0 = 0.f, rs1 = 0.f;
        float iv0 = 0.f, iv1 = 0.f;
        if (MODE == 2) {
            // inline rowsum: 4 partials per row
            float4 a0 = *reinterpret_cast<const float4*>(aux0 + (size_t)r0 * 4);
            float4 b0 = *reinterpret_cast<const float4*>(aux0 + (size_t)(r0 + 8) * 4);
            iv0 = 1.f / ((a0.x + a0.y) + (a0.z + a0.w));
            iv1 = 1.f / ((b0.x + b0.y) + (b0.z + b0.w));
        }
        #pragma unroll
        for (int nj = 0; nj < 8; nj++) {
            int c0 = n0 + warpN * 64 + nj * 8 + cb;
            __half2 h0 = *reinterpret_cast<__half2*>(&acc[mi][nj][0]); // row r0
            __half2 h1 = *reinterpret_cast<__half2*>(&acc[mi][nj][1]); // row r0+8
            if (MODE == 0) {
                __half* D = (__half*)dst;
                *reinterpret_cast<__half2*>(D + (size_t)r0 * NNEU + c0) = h0;
                *reinterpret_cast<__half2*>(D + (size_t)(r0 + 8) * NNEU + c0) = h1;
            } else if (MODE == 1) {
                __half* D = (__half*)dst;
                float2 f0 = __half22float2(h0);
                float2 f1 = __half22float2(h1);
                float xs0 = aux0[r0], xs1 = aux0[r0 + 8];
                float pq0 = aux1[c0], pq1 = aux1[c0 + 1];
                float sc0 = aux2[c0], sc1 = aux2[c0 + 1];
                float d00 = sqrtf(fmaxf(xs0 + pq0 - 2.f * f0.x, 0.f));
                float d01 = sqrtf(fmaxf(xs0 + pq1 - 2.f * f0.y, 0.f));
                float d10 = sqrtf(fmaxf(xs1 + pq0 - 2.f * f1.x, 0.f));
                float d11 = sqrtf(fmaxf(xs1 + pq1 - 2.f * f1.y, 0.f));
                float e00 = __expf(sc0 / (d00 + 0.1f));
                float e01 = __expf(sc1 / (d01 + 0.1f));
                float e10 = __expf(sc0 / (d10 + 0.1f));
                float e11 = __expf(sc1 / (d11 + 0.1f));
                rs0 += e00 + e01;
                rs1 += e10 + e11;
                *reinterpret_cast<__half2*>(D + (size_t)r0 * NNEU + c0) =
                    __floats2half2_rn(e00, e01);
                *reinterpret_cast<__half2*>(D + (size_t)(r0 + 8) * NNEU + c0) =
                    __floats2half2_rn(e10, e11);
            } else {
                float* D = (float*)dst;
                float2 f0 = __half22float2(h0);
                float2 f1 = __half22float2(h1);
                float b0 = aux1[c0], b1 = aux1[c0 + 1];
                float2 o0 = make_float2(f0.x * iv0 + b0, f0.y * iv0 + b1);
                float2 o1 = make_float2(f1.x * iv1 + b0, f1.y * iv1 + b1);
                *reinterpret_cast<float2*>(D + (size_t)r0 * DIM + c0) = o0;
                *reinterpret_cast<float2*>(D + (size_t)(r0 + 8) * DIM + c0) = o1;
            }
        }
        if (MODE == 1) {
            // reduce over the 4 lanes of the quad (cols), leave on lane&3==0
            rs0 += __shfl_xor_sync(0xffffffffu, rs0, 1);
            rs0 += __shfl_xor_sync(0xffffffffu, rs0, 2);
            rs1 += __shfl_xor_sync(0xffffffffu, rs1, 1);
            rs1 += __shfl_xor_sync(0xffffffffu, rs1, 2);
            if ((lane & 3) == 0) {
                rs_sm[rt0 * 4 + warpN] = rs0;
                rs_sm[(rt0 + 8) * 4 + warpN] = rs1;
            }
        }
    }
    if (MODE == 1) {
        __syncthreads();
        if (tid < 128) {
            float4 v = reinterpret_cast<const float4*>(rs_sm)[tid];
            g_rsp[(size_t)(m0 + tid) * 4 + blockIdx.y] =
                (v.x + v.y) + (v.z + v.w);
        }
    }
}

// ============================================================================
// Host launcher — fork/join second stream for conv+VWt overlap with
// rowsq+scores. Stream/events created on first (uncaptured) call only.
// ============================================================================
extern "C" void kernel_launch(void* const* d_in, const int* in_sizes, int n_in,
                              void* d_out, int out_size) {
    (void)in_sizes; (void)n_in; (void)out_size;
    const float* x      = (const float*)d_in[0];
    const float* pos    = (const float*)d_in[1];
    const float* scales = (const float*)d_in[2];
    const float* values = (const float*)d_in[3];
    const float* W      = (const float*)d_in[4];
    const float* b      = (const float*)d_in[5];
    float* out = (float*)d_out;

    static __half* vwt_p = nullptr;
    static __half* E_p   = nullptr;
    static float *xsq_p, *psq_p, *rsp_p;
    static __half *xb_p, *pb_p, *vb_p, *wb_p;
    static cudaStream_t s2;
    static cudaEvent_t eFork, eJoin;
    if (!vwt_p) {
        cudaGetSymbolAddress((void**)&vwt_p, g_vwt);
        cudaGetSymbolAddress((void**)&E_p,   g_E);
        cudaGetSymbolAddress((void**)&xsq_p, g_xsq);
        cudaGetSymbolAddress((void**)&psq_p, g_psq);
        cudaGetSymbolAddress((void**)&rsp_p, g_rsp);
        cudaGetSymbolAddress((void**)&xb_p,  g_xb);
        cudaGetSymbolAddress((void**)&pb_p,  g_pb);
        cudaGetSymbolAddress((void**)&vb_p,  g_vb);
        cudaGetSymbolAddress((void**)&wb_p,  g_wb);
        cudaStreamCreateWithFlags(&s2, cudaStreamNonBlocking);
        cudaEventCreateWithFlags(&eFork, cudaEventDisableTiming);
        cudaEventCreateWithFlags(&eJoin, cudaEventDisableTiming);
        cudaFuncSetAttribute(k_gemm<512, 0>,
            cudaFuncAttributeMaxDynamicSharedMemorySize, SMEM_SZ);
        cudaFuncSetAttribute(k_gemm<512, 1>,
            cudaFuncAttributeMaxDynamicSharedMemorySize, SMEM_SZ);
        cudaFuncSetAttribute(k_gemm<1024, 2>,
            cudaFuncAttributeMaxDynamicSharedMemorySize, SMEM_SZ);
    }

    // fork side stream: conv -> VWt GEMM (independent of x path)
    cudaEventRecord(eFork, 0);
    cudaStreamWaitEvent(s2, eFork, 0);
    k_conv<<<((NNEU * DIM + DIM * DIM) / 4) / 256, 256, 0, s2>>>(values, W);
    k_gemm<512, 0><<<dim3(4, 4), 256, SMEM_SZ, s2>>>(
        wb_p, vb_p, vwt_p, nullptr, nullptr, nullptr);
    cudaEventRecord(eJoin, s2);

    // main stream: rowsq -> scores
    k_rowsq<<<(MTOT + NNEU) / 8, 256>>>(x, pos);
    k_gemm<512, 1><<<dim3(128, 4), 256, SMEM_SZ>>>(
        xb_p, pb_p, E_p, xsq_p, psq_p, scales);

    // join, then out = E @ VWt^T / rowsum + b   (rowsum inlined from g_rsp)
    cudaStreamWaitEvent(0, eJoin, 0);
    k_gemm<1024, 2><<<dim3(128, 2), 256, SMEM_SZ>>>(
        E_p, vwt_p, out, rsp_p, b, nullptr);
}

// round 16
// speedup vs baseline: 1.0534x; 1.0033x over previous
#include <cuda_runtime.h>
#include <cuda_fp16.h>
#include <cstdint>

// ============================================================================
// CrystalAttention, sm_100-baseline ISA (mma.sync + cp.async; no tcgen05).
//   VWt[d][n] = sum_k W[d,k] V[n,k]
//   S = X @ P^T ; E = exp(scales/(sqrt(max(xsq+psq-2S,0))+0.1))
//   out = (E @ VWt^T) / rowsum(E) + b_out
// M=16384, D=512, N=1024.
// R16: exact R11 GEMM core (fp16 f16-accum, 128x128 CTA tile, 32x64 warp
// tile, 2-stage, 1 sync/chunk, 3 CTAs/SM). Schedule change only: M-halved
// E and out GEMMs cross-overlapped on a third stream (out(h1) || E(h2)).
// ============================================================================
#define MTOT 16384
#define DIM  512
#define NNEU 1024

__device__ __half  g_xb[(size_t)MTOT * DIM];
__device__ float   g_xsq[MTOT];
__device__ __half  g_pb[(size_t)NNEU * DIM];
__device__ float   g_psq[NNEU];
__device__ __half  g_vb[(size_t)NNEU * DIM];
__device__ __half  g_wb[(size_t)DIM * DIM];
__device__ __half  g_vwt[(size_t)DIM * NNEU];
__device__ __half  g_E[(size_t)MTOT * NNEU];
__device__ float   g_rsp[(size_t)MTOT * 8];   // partial rowsums per nb

// ============================================================================
// helpers
// ============================================================================
__device__ __forceinline__ uint32_t smem_u32(const void* p) {
    uint32_t a;
    asm("{ .reg .u64 t; cvta.to.shared.u64 t, %1; cvt.u32.u64 %0, t; }"
        : "=r"(a) : "l"(p));
    return a;
}

#define CP_ASYNC16(saddr, gaddr) \
    asm volatile("cp.async.cg.shared.global [%0], [%1], 16;\n" \
                 :: "r"(saddr), "l"(gaddr) : "memory")
#define CP_COMMIT() asm volatile("cp.async.commit_group;\n" ::: "memory")
#define CP_WAIT(n)  asm volatile("cp.async.wait_group %0;\n" :: "n"(n) : "memory")

__device__ __forceinline__ void ldsm_x4(uint32_t* f, uint32_t addr) {
    asm volatile("ldmatrix.sync.aligned.m8n8.x4.shared.b16 {%0,%1,%2,%3}, [%4];\n"
                 : "=r"(f[0]), "=r"(f[1]), "=r"(f[2]), "=r"(f[3]) : "r"(addr));
}

// f16-accumulate MMA: D(f16x2 x2) = A(f16 x4) * B(f16 x2) + D
__device__ __forceinline__ void mma16816_f16(uint32_t* d, const uint32_t* a,
                                             const uint32_t* b) {
    asm volatile(
        "mma.sync.aligned.m16n8k16.row.col.f16.f16.f16.f16 "
        "{%0,%1}, {%2,%3,%4,%5}, {%6,%7}, {%0,%1};\n"
        : "+r"(d[0]), "+r"(d[1])
        : "r"(a[0]), "r"(a[1]), "r"(a[2]), "r"(a[3]), "r"(b[0]), "r"(b[1]));
}

// swizzled smem byte offset, 128B pitch rows, b16 col c (c%8==0)
__device__ __forceinline__ uint32_t sw_off(int r, int c) {
    return (uint32_t)(r * 128 + ((((c >> 3) ^ (r & 7))) << 4));
}

// ============================================================================
// prep: fp32->fp16 + row sum-of-squares. One warp per row, 4 float4 per lane.
// ============================================================================
__global__ void k_rowsq(const float* __restrict__ x, const float* __restrict__ pos) {
    int gw = blockIdx.x * 8 + (threadIdx.x >> 5);
    int lane = threadIdx.x & 31;
    const float* src;
    __half* dstB;
    float* dstS;
    int r;
    if (gw < MTOT) { src = x;   dstB = g_xb; dstS = g_xsq; r = gw; }
    else           { src = pos; dstB = g_pb; dstS = g_psq; r = gw - MTOT; }

    const float4* p = reinterpret_cast<const float4*>(src) + (size_t)r * (DIM / 4);
    uint2* q = reinterpret_cast<uint2*>(dstB) + (size_t)r * (DIM / 4);
    float s = 0.f;
    #pragma unroll
    for (int i = 0; i < 4; i++) {
        float4 v = p[lane + 32 * i];
        __half2 p0 = __floats2half2_rn(v.x, v.y);
        __half2 p1 = __floats2half2_rn(v.z, v.w);
        uint2 u;
        u.x = *reinterpret_cast<uint32_t*>(&p0);
        u.y = *reinterpret_cast<uint32_t*>(&p1);
        q[lane + 32 * i] = u;
        s += v.x * v.x + v.y * v.y + v.z * v.z + v.w * v.w;
    }
    #pragma unroll
    for (int off = 16; off > 0; off >>= 1)
        s += __shfl_xor_sync(0xffffffffu, s, off);
    if (lane == 0) dstS[r] = s;
}

// prep: fp32->fp16 for values then W_out, one grid
__global__ void k_conv(const float* __restrict__ values, const float* __restrict__ W) {
    constexpr int NV4 = (NNEU * DIM) / 4;   // 131072
    int i = blockIdx.x * blockDim.x + threadIdx.x;
    const float* src;
    __half* dst;
    int j;
    if (i < NV4) { src = values; dst = g_vb; j = i; }
    else         { src = W;      dst = g_wb; j = i - NV4; }
    float4 v = reinterpret_cast<const float4*>(src)[j];
    __half2 p0 = __floats2half2_rn(v.x, v.y);
    __half2 p1 = __floats2half2_rn(v.z, v.w);
    uint2 u;
    u.x = *reinterpret_cast<uint32_t*>(&p0);
    u.y = *reinterpret_cast<uint32_t*>(&p1);
    reinterpret_cast<uint2*>(dst)[j] = u;
}

// ============================================================================
// GEMM: C = A @ B^T. CTA tile 128(M) x 128(N), K chunk 64, 2-stage cp.async,
// single __syncthreads per chunk (wait -> barrier -> prefetch -> compute).
// 256 threads: warpM = wid>>1 (4), warpN = wid&1 (2); warp tile 32x64,
// f16 accumulators. 3 CTAs/SM. mbase = global row offset of this launch.
// MODE 0: f16 store (VWt)     MODE 1: E=exp(score), f16 + partial rowsum
// MODE 2: out = acc/rowsum(8 partials inline) + b, fp32
// ============================================================================
constexpr int STG    = 32768;            // bytes per stage (A 16KB + B 16KB)
constexpr int SM_RS  = 2 * STG;          // rowsum scratch (128*2 floats)
constexpr int SMEM_SZ = SM_RS + 1024;    // 66560 B/CTA; 3 CTAs = 195 KB

template<int KTOT, int MODE>
__global__ void __launch_bounds__(256, 3) k_gemm(
    const __half* __restrict__ Ag,
    const __half* __restrict__ Bg,
    void* __restrict__ dst,
    const float* __restrict__ aux0,   // xsq (M1) / rsp partials (M2)
    const float* __restrict__ aux1,   // psq (M1) / bout  (M2)
    const float* __restrict__ aux2,   // scales (M1)
    int mbase)
{
    constexpr int NC = KTOT / 64;
    extern __shared__ char smem[];
    const uint32_t sbase = smem_u32(smem);

    const int tid = threadIdx.x;
    const int lane = tid & 31, wid = tid >> 5;
    const int warpM = wid >> 1, warpN = wid & 1;
    const int m0 = mbase + blockIdx.x * 128;
    const int n0 = blockIdx.y * 128;

    auto prefetch = [&](int kc) {
        const __half* Ab = Ag + (size_t)m0 * KTOT + kc * 64;
        const __half* Bb = Bg + (size_t)n0 * KTOT + kc * 64;
        uint32_t da = sbase + (kc & 1) * STG;
        uint32_t db = da + 16384;
        #pragma unroll
        for (int it = 0; it < 4; it++) {          // A: 128 rows x 8 chunks
            int i = tid + it * 256;
            int r = i >> 3, ch = i & 7;
            CP_ASYNC16(da + sw_off(r, ch * 8), Ab + (size_t)r * KTOT + ch * 8);
        }
        #pragma unroll
        for (int it = 0; it < 4; it++) {          // B: 128 rows x 8 chunks
            int i = tid + it * 256;
            int r = i >> 3, ch = i & 7;
            CP_ASYNC16(db + sw_off(r, ch * 8), Bb + (size_t)r * KTOT + ch * 8);
        }
        CP_COMMIT();
    };

    uint32_t acc[2][8][2];    // f16x2 accumulators
    #pragma unroll
    for (int i = 0; i < 2; i++)
        #pragma unroll
        for (int j = 0; j < 8; j++) { acc[i][j][0] = 0u; acc[i][j][1] = 0u; }

    prefetch(0);

    for (int c = 0; c < NC; c++) {
        // Wait for own copies of chunk c, then barrier: makes all threads'
        // chunk-c data globally visible AND proves all warps finished
        // compute(c-1) -> buffer (c+1)&1 == (c-1)&1 is free for prefetch.
        CP_WAIT(0);
        __syncthreads();
        if (c + 1 < NC) prefetch(c + 1);

        uint32_t sa = sbase + (c & 1) * STG;
        uint32_t sb = sa + 16384;

        #pragma unroll
        for (int ks = 0; ks < 4; ks++) {
            uint32_t af[2][4], bfr[8][2];
            #pragma unroll
            for (int mi = 0; mi < 2; mi++) {
                int r = warpM * 32 + mi * 16 + (lane & 15);
                int cc = ks * 16 + ((lane >> 4) << 3);
                ldsm_x4(af[mi], sa + sw_off(r, cc));
            }
            #pragma unroll
            for (int nb = 0; nb < 4; nb++) {
                int r = warpN * 64 + nb * 16 + ((lane >> 4) << 3) + (lane & 7);
                int cc = ks * 16 + (((lane >> 3) & 1) << 3);
                uint32_t f[4];
                ldsm_x4(f, sb + sw_off(r, cc));
                bfr[2 * nb][0] = f[0]; bfr[2 * nb][1] = f[1];
                bfr[2 * nb + 1][0] = f[2]; bfr[2 * nb + 1][1] = f[3];
            }
            #pragma unroll
            for (int mi = 0; mi < 2; mi++)
                #pragma unroll
                for (int nj = 0; nj < 8; nj++)
                    mma16816_f16(acc[mi][nj], af[mi], bfr[nj]);
        }
    }
    __syncthreads();

    // ---- epilogue ----
    const int rb = lane >> 2;
    const int cb = (lane & 3) * 2;
    float* rs_sm = reinterpret_cast<float*>(smem + SM_RS);

    #pragma unroll
    for (int mi = 0; mi < 2; mi++) {
        int rt0 = warpM * 32 + mi * 16 + rb;       // row in tile; +8 for second
        int r0 = m0 + rt0;
        float rs0 = 0.f, rs1 = 0.f;
        float iv0 = 0.f, iv1 = 0.f;
        if (MODE == 2) {
            // inline rowsum: 8 partials per row
            float4 a0 = *reinterpret_cast<const float4*>(aux0 + (size_t)r0 * 8);
            float4 a1 = *reinterpret_cast<const float4*>(aux0 + (size_t)r0 * 8 + 4);
            float4 b0 = *reinterpret_cast<const float4*>(aux0 + (size_t)(r0 + 8) * 8);
            float4 b1 = *reinterpret_cast<const float4*>(aux0 + (size_t)(r0 + 8) * 8 + 4);
            iv0 = 1.f / ((a0.x + a0.y + a0.z + a0.w) + (a1.x + a1.y + a1.z + a1.w));
            iv1 = 1.f / ((b0.x + b0.y + b0.z + b0.w) + (b1.x + b1.y + b1.z + b1.w));
        }
        #pragma unroll
        for (int nj = 0; nj < 8; nj++) {
            int c0 = n0 + warpN * 64 + nj * 8 + cb;
            __half2 h0 = *reinterpret_cast<__half2*>(&acc[mi][nj][0]); // row r0
            __half2 h1 = *reinterpret_cast<__half2*>(&acc[mi][nj][1]); // row r0+8
            if (MODE == 0) {
                __half* D = (__half*)dst;
                *reinterpret_cast<__half2*>(D + (size_t)r0 * NNEU + c0) = h0;
                *reinterpret_cast<__half2*>(D + (size_t)(r0 + 8) * NNEU + c0) = h1;
            } else if (MODE == 1) {
                __half* D = (__half*)dst;
                float2 f0 = __half22float2(h0);
                float2 f1 = __half22float2(h1);
                float xs0 = aux0[r0], xs1 = aux0[r0 + 8];
                float pq0 = aux1[c0], pq1 = aux1[c0 + 1];
                float sc0 = aux2[c0], sc1 = aux2[c0 + 1];
                float d00 = sqrtf(fmaxf(xs0 + pq0 - 2.f * f0.x, 0.f));
                float d01 = sqrtf(fmaxf(xs0 + pq1 - 2.f * f0.y, 0.f));
                float d10 = sqrtf(fmaxf(xs1 + pq0 - 2.f * f1.x, 0.f));
                float d11 = sqrtf(fmaxf(xs1 + pq1 - 2.f * f1.y, 0.f));
                float e00 = __expf(sc0 / (d00 + 0.1f));
                float e01 = __expf(sc1 / (d01 + 0.1f));
                float e10 = __expf(sc0 / (d10 + 0.1f));
                float e11 = __expf(sc1 / (d11 + 0.1f));
                rs0 += e00 + e01;
                rs1 += e10 + e11;
                *reinterpret_cast<__half2*>(D + (size_t)r0 * NNEU + c0) =
                    __floats2half2_rn(e00, e01);
                *reinterpret_cast<__half2*>(D + (size_t)(r0 + 8) * NNEU + c0) =
                    __floats2half2_rn(e10, e11);
            } else {
                float* D = (float*)dst;
                float2 f0 = __half22float2(h0);
                float2 f1 = __half22float2(h1);
                float b0 = aux1[c0], b1 = aux1[c0 + 1];
                float2 o0 = make_float2(f0.x * iv0 + b0, f0.y * iv0 + b1);
                float2 o1 = make_float2(f1.x * iv1 + b0, f1.y * iv1 + b1);
                *reinterpret_cast<float2*>(D + (size_t)r0 * DIM + c0) = o0;
                *reinterpret_cast<float2*>(D + (size_t)(r0 + 8) * DIM + c0) = o1;
            }
        }
        if (MODE == 1) {
            // reduce over the 4 lanes of the quad (cols), leave on lane&3==0
            rs0 += __shfl_xor_sync(0xffffffffu, rs0, 1);
            rs0 += __shfl_xor_sync(0xffffffffu, rs0, 2);
            rs1 += __shfl_xor_sync(0xffffffffu, rs1, 1);
            rs1 += __shfl_xor_sync(0xffffffffu, rs1, 2);
            if ((lane & 3) == 0) {
                rs_sm[rt0 * 2 + warpN] = rs0;
                rs_sm[(rt0 + 8) * 2 + warpN] = rs1;
            }
        }
    }
    if (MODE == 1) {
        __syncthreads();
        if (tid < 128) {
            float2 v = reinterpret_cast<const float2*>(rs_sm)[tid];
            g_rsp[(size_t)(m0 + tid) * 8 + blockIdx.y] = v.x + v.y;
        }
    }
}

// ============================================================================
// Host launcher — 3 streams:
//   s2: conv -> VWt
//   main: rowsq -> E(h1) -> E(h2)
//   s3: (after E(h1), VWt) out(h1) ; (after E(h2)) out(h2)
// out(h1) overlaps E(h2). Resources created on first (uncaptured) call.
// ============================================================================
extern "C" void kernel_launch(void* const* d_in, const int* in_sizes, int n_in,
                              void* d_out, int out_size) {
    (void)in_sizes; (void)n_in; (void)out_size;
    const float* x      = (const float*)d_in[0];
    const float* pos    = (const float*)d_in[1];
    const float* scales = (const float*)d_in[2];
    const float* values = (const float*)d_in[3];
    const float* W      = (const float*)d_in[4];
    const float* b      = (const float*)d_in[5];
    float* out = (float*)d_out;

    static __half* vwt_p = nullptr;
    static __half* E_p   = nullptr;
    static float *xsq_p, *psq_p, *rsp_p;
    static __half *xb_p, *pb_p, *vb_p, *wb_p;
    static cudaStream_t s2, s3;
    static cudaEvent_t eFork, eJoin, eE1, eE2, eOut;
    if (!vwt_p) {
        cudaGetSymbolAddress((void**)&vwt_p, g_vwt);
        cudaGetSymbolAddress((void**)&E_p,   g_E);
        cudaGetSymbolAddress((void**)&xsq_p, g_xsq);
        cudaGetSymbolAddress((void**)&psq_p, g_psq);
        cudaGetSymbolAddress((void**)&rsp_p, g_rsp);
        cudaGetSymbolAddress((void**)&xb_p,  g_xb);
        cudaGetSymbolAddress((void**)&pb_p,  g_pb);
        cudaGetSymbolAddress((void**)&vb_p,  g_vb);
        cudaGetSymbolAddress((void**)&wb_p,  g_wb);
        cudaStreamCreateWithFlags(&s2, cudaStreamNonBlocking);
        cudaStreamCreateWithFlags(&s3, cudaStreamNonBlocking);
        cudaEventCreateWithFlags(&eFork, cudaEventDisableTiming);
        cudaEventCreateWithFlags(&eJoin, cudaEventDisableTiming);
        cudaEventCreateWithFlags(&eE1,   cudaEventDisableTiming);
        cudaEventCreateWithFlags(&eE2,   cudaEventDisableTiming);
        cudaEventCreateWithFlags(&eOut,  cudaEventDisableTiming);
        cudaFuncSetAttribute(k_gemm<512, 0>,
            cudaFuncAttributeMaxDynamicSharedMemorySize, SMEM_SZ);
        cudaFuncSetAttribute(k_gemm<512, 1>,
            cudaFuncAttributeMaxDynamicSharedMemorySize, SMEM_SZ);
        cudaFuncSetAttribute(k_gemm<1024, 2>,
            cudaFuncAttributeMaxDynamicSharedMemorySize, SMEM_SZ);
    }

    // fork side stream: conv -> VWt GEMM (independent of x path)
    cudaEventRecord(eFork, 0);
    cudaStreamWaitEvent(s2, eFork, 0);
    k_conv<<<((NNEU * DIM + DIM * DIM) / 4) / 256, 256, 0, s2>>>(values, W);
    k_gemm<512, 0><<<dim3(4, 8), 256, SMEM_SZ, s2>>>(
        wb_p, vb_p, vwt_p, nullptr, nullptr, nullptr, 0);
    cudaEventRecord(eJoin, s2);

    // main stream: rowsq -> E half 1 -> E half 2
    k_rowsq<<<(MTOT + NNEU) / 8, 256>>>(x, pos);
    k_gemm<512, 1><<<dim3(64, 8), 256, SMEM_SZ>>>(
        xb_p, pb_p, E_p, xsq_p, psq_p, scales, 0);
    cudaEventRecord(eE1, 0);
    k_gemm<512, 1><<<dim3(64, 8), 256, SMEM_SZ>>>(
        xb_p, pb_p, E_p, xsq_p, psq_p, scales, MTOT / 2);
    cudaEventRecord(eE2, 0);

    // s3: out half 1 (needs E1 + VWt), overlaps E half 2; then out half 2
    cudaStreamWaitEvent(s3, eE1, 0);
    cudaStreamWaitEvent(s3, eJoin, 0);
    k_gemm<1024, 2><<<dim3(64, 4), 256, SMEM_SZ, s3>>>(
        E_p, vwt_p, out, rsp_p, b, nullptr, 0);
    cudaStreamWaitEvent(s3, eE2, 0);
    k_gemm<1024, 2><<<dim3(64, 4), 256, SMEM_SZ, s3>>>(
        E_p, vwt_p, out, rsp_p, b, nullptr, MTOT / 2);
    cudaEventRecord(eOut, s3);

    // join back to the capture stream
    cudaStreamWaitEvent(0, eOut, 0);
}

// round 17
// speedup vs baseline: 1.1061x; 1.0501x over previous
#include <cuda_runtime.h>
#include <cuda_fp16.h>
#include <cstdint>

// ============================================================================
// CrystalAttention, sm_100-baseline ISA (mma.sync + cp.async; no tcgen05).
//   VWt[d][n] = sum_k W[d,k] V[n,k]
//   S = X @ P^T ; E = exp(scales/(sqrt(max(xsq+psq-2S,0))+0.1))
//   out = (E @ VWt^T) / rowsum(E) + b_out
// M=16384, D=512, N=1024.
// R17 == R11 (champion, 137.5us): fp16 pipeline, f16-accum mma, 128x128 CTA
// tile, 32x64 warp tile, 2-stage cp.async (wait -> barrier -> prefetch),
// 3 CTAs/SM, dual-stream conv+VWt overlap, fused rowsum partials.
// ============================================================================
#define MTOT 16384
#define DIM  512
#define NNEU 1024

__device__ __half  g_xb[(size_t)MTOT * DIM];
__device__ float   g_xsq[MTOT];
__device__ __half  g_pb[(size_t)NNEU * DIM];
__device__ float   g_psq[NNEU];
__device__ __half  g_vb[(size_t)NNEU * DIM];
__device__ __half  g_wb[(size_t)DIM * DIM];
__device__ __half  g_vwt[(size_t)DIM * NNEU];
__device__ __half  g_E[(size_t)MTOT * NNEU];
__device__ float   g_rsp[(size_t)MTOT * 8];   // partial rowsums per nb

// ============================================================================
// helpers
// ============================================================================
__device__ __forceinline__ uint32_t smem_u32(const void* p) {
    uint32_t a;
    asm("{ .reg .u64 t; cvta.to.shared.u64 t, %1; cvt.u32.u64 %0, t; }"
        : "=r"(a) : "l"(p));
    return a;
}

#define CP_ASYNC16(saddr, gaddr) \
    asm volatile("cp.async.cg.shared.global [%0], [%1], 16;\n" \
                 :: "r"(saddr), "l"(gaddr) : "memory")
#define CP_COMMIT() asm volatile("cp.async.commit_group;\n" ::: "memory")
#define CP_WAIT(n)  asm volatile("cp.async.wait_group %0;\n" :: "n"(n) : "memory")

__device__ __forceinline__ void ldsm_x4(uint32_t* f, uint32_t addr) {
    asm volatile("ldmatrix.sync.aligned.m8n8.x4.shared.b16 {%0,%1,%2,%3}, [%4];\n"
                 : "=r"(f[0]), "=r"(f[1]), "=r"(f[2]), "=r"(f[3]) : "r"(addr));
}

// f16-accumulate MMA: D(f16x2 x2) = A(f16 x4) * B(f16 x2) + D
__device__ __forceinline__ void mma16816_f16(uint32_t* d, const uint32_t* a,
                                             const uint32_t* b) {
    asm volatile(
        "mma.sync.aligned.m16n8k16.row.col.f16.f16.f16.f16 "
        "{%0,%1}, {%2,%3,%4,%5}, {%6,%7}, {%0,%1};\n"
        : "+r"(d[0]), "+r"(d[1])
        : "r"(a[0]), "r"(a[1]), "r"(a[2]), "r"(a[3]), "r"(b[0]), "r"(b[1]));
}

// swizzled smem byte offset, 128B pitch rows, b16 col c (c%8==0)
__device__ __forceinline__ uint32_t sw_off(int r, int c) {
    return (uint32_t)(r * 128 + ((((c >> 3) ^ (r & 7))) << 4));
}

// ============================================================================
// prep: fp32->fp16 + row sum-of-squares. One warp per row, 4 float4 per lane.
// ============================================================================
__global__ void k_rowsq(const float* __restrict__ x, const float* __restrict__ pos) {
    int gw = blockIdx.x * 8 + (threadIdx.x >> 5);
    int lane = threadIdx.x & 31;
    const float* src;
    __half* dstB;
    float* dstS;
    int r;
    if (gw < MTOT) { src = x;   dstB = g_xb; dstS = g_xsq; r = gw; }
    else           { src = pos; dstB = g_pb; dstS = g_psq; r = gw - MTOT; }

    const float4* p = reinterpret_cast<const float4*>(src) + (size_t)r * (DIM / 4);
    uint2* q = reinterpret_cast<uint2*>(dstB) + (size_t)r * (DIM / 4);
    float s = 0.f;
    #pragma unroll
    for (int i = 0; i < 4; i++) {
        float4 v = p[lane + 32 * i];
        __half2 p0 = __floats2half2_rn(v.x, v.y);
        __half2 p1 = __floats2half2_rn(v.z, v.w);
        uint2 u;
        u.x = *reinterpret_cast<uint32_t*>(&p0);
        u.y = *reinterpret_cast<uint32_t*>(&p1);
        q[lane + 32 * i] = u;
        s += v.x * v.x + v.y * v.y + v.z * v.z + v.w * v.w;
    }
    #pragma unroll
    for (int off = 16; off > 0; off >>= 1)
        s += __shfl_xor_sync(0xffffffffu, s, off);
    if (lane == 0) dstS[r] = s;
}

// prep: fp32->fp16 for values then W_out, one grid
__global__ void k_conv(const float* __restrict__ values, const float* __restrict__ W) {
    constexpr int NV4 = (NNEU * DIM) / 4;   // 131072
    int i = blockIdx.x * blockDim.x + threadIdx.x;
    const float* src;
    __half* dst;
    int j;
    if (i < NV4) { src = values; dst = g_vb; j = i; }
    else         { src = W;      dst = g_wb; j = i - NV4; }
    float4 v = reinterpret_cast<const float4*>(src)[j];
    __half2 p0 = __floats2half2_rn(v.x, v.y);
    __half2 p1 = __floats2half2_rn(v.z, v.w);
    uint2 u;
    u.x = *reinterpret_cast<uint32_t*>(&p0);
    u.y = *reinterpret_cast<uint32_t*>(&p1);
    reinterpret_cast<uint2*>(dst)[j] = u;
}

// ============================================================================
// GEMM: C = A @ B^T. CTA tile 128(M) x 128(N), K chunk 64, 2-stage cp.async,
// single __syncthreads per chunk (wait -> barrier -> prefetch -> compute).
// 256 threads: warpM = wid>>1 (4), warpN = wid&1 (2); warp tile 32x64,
// f16 accumulators. 3 CTAs/SM.
// MODE 0: f16 store (VWt)     MODE 1: E=exp(score), f16 + partial rowsum
// MODE 2: out = acc/rowsum(8 partials inline) + b, fp32
// ============================================================================
constexpr int STG    = 32768;            // bytes per stage (A 16KB + B 16KB)
constexpr int SM_RS  = 2 * STG;          // rowsum scratch (128*2 floats)
constexpr int SMEM_SZ = SM_RS + 1024;    // 66560 B/CTA; 3 CTAs = 195 KB

template<int KTOT, int MODE>
__global__ void __launch_bounds__(256, 3) k_gemm(
    const __half* __restrict__ Ag,
    const __half* __restrict__ Bg,
    void* __restrict__ dst,
    const float* __restrict__ aux0,   // xsq (M1) / rsp partials (M2)
    const float* __restrict__ aux1,   // psq (M1) / bout  (M2)
    const float* __restrict__ aux2)   // scales (M1)
{
    constexpr int NC = KTOT / 64;
    extern __shared__ char smem[];
    const uint32_t sbase = smem_u32(smem);

    const int tid = threadIdx.x;
    const int lane = tid & 31, wid = tid >> 5;
    const int warpM = wid >> 1, warpN = wid & 1;
    const int m0 = blockIdx.x * 128;
    const int n0 = blockIdx.y * 128;

    auto prefetch = [&](int kc) {
        const __half* Ab = Ag + (size_t)m0 * KTOT + kc * 64;
        const __half* Bb = Bg + (size_t)n0 * KTOT + kc * 64;
        uint32_t da = sbase + (kc & 1) * STG;
        uint32_t db = da + 16384;
        #pragma unroll
        for (int it = 0; it < 4; it++) {          // A: 128 rows x 8 chunks
            int i = tid + it * 256;
            int r = i >> 3, ch = i & 7;
            CP_ASYNC16(da + sw_off(r, ch * 8), Ab + (size_t)r * KTOT + ch * 8);
        }
        #pragma unroll
        for (int it = 0; it < 4; it++) {          // B: 128 rows x 8 chunks
            int i = tid + it * 256;
            int r = i >> 3, ch = i & 7;
            CP_ASYNC16(db + sw_off(r, ch * 8), Bb + (size_t)r * KTOT + ch * 8);
        }
        CP_COMMIT();
    };

    uint32_t acc[2][8][2];    // f16x2 accumulators
    #pragma unroll
    for (int i = 0; i < 2; i++)
        #pragma unroll
        for (int j = 0; j < 8; j++) { acc[i][j][0] = 0u; acc[i][j][1] = 0u; }

    prefetch(0);

    for (int c = 0; c < NC; c++) {
        // Wait for own copies of chunk c, then barrier: makes all threads'
        // chunk-c data globally visible AND proves all warps finished
        // compute(c-1) -> buffer (c+1)&1 == (c-1)&1 is free for prefetch.
        CP_WAIT(0);
        __syncthreads();
        if (c + 1 < NC) prefetch(c + 1);

        uint32_t sa = sbase + (c & 1) * STG;
        uint32_t sb = sa + 16384;

        #pragma unroll
        for (int ks = 0; ks < 4; ks++) {
            uint32_t af[2][4], bfr[8][2];
            #pragma unroll
            for (int mi = 0; mi < 2; mi++) {
                int r = warpM * 32 + mi * 16 + (lane & 15);
                int cc = ks * 16 + ((lane >> 4) << 3);
                ldsm_x4(af[mi], sa + sw_off(r, cc));
            }
            #pragma unroll
            for (int nb = 0; nb < 4; nb++) {
                int r = warpN * 64 + nb * 16 + ((lane >> 4) << 3) + (lane & 7);
                int cc = ks * 16 + (((lane >> 3) & 1) << 3);
                uint32_t f[4];
                ldsm_x4(f, sb + sw_off(r, cc));
                bfr[2 * nb][0] = f[0]; bfr[2 * nb][1] = f[1];
                bfr[2 * nb + 1][0] = f[2]; bfr[2 * nb + 1][1] = f[3];
            }
            #pragma unroll
            for (int mi = 0; mi < 2; mi++)
                #pragma unroll
                for (int nj = 0; nj < 8; nj++)
                    mma16816_f16(acc[mi][nj], af[mi], bfr[nj]);
        }
    }
    __syncthreads();

    // ---- epilogue ----
    const int rb = lane >> 2;
    const int cb = (lane & 3) * 2;
    float* rs_sm = reinterpret_cast<float*>(smem + SM_RS);

    #pragma unroll
    for (int mi = 0; mi < 2; mi++) {
        int rt0 = warpM * 32 + mi * 16 + rb;       // row in tile; +8 for second
        int r0 = m0 + rt0;
        float rs0 = 0.f, rs1 = 0.f;
        float iv0 = 0.f, iv1 = 0.f;
        if (MODE == 2) {
            // inline rowsum: 8 partials per row
            float4 a0 = *reinterpret_cast<const float4*>(aux0 + (size_t)r0 * 8);
            float4 a1 = *reinterpret_cast<const float4*>(aux0 + (size_t)r0 * 8 + 4);
            float4 b0 = *reinterpret_cast<const float4*>(aux0 + (size_t)(r0 + 8) * 8);
            float4 b1 = *reinterpret_cast<const float4*>(aux0 + (size_t)(r0 + 8) * 8 + 4);
            iv0 = 1.f / ((a0.x + a0.y + a0.z + a0.w) + (a1.x + a1.y + a1.z + a1.w));
            iv1 = 1.f / ((b0.x + b0.y + b0.z + b0.w) + (b1.x + b1.y + b1.z + b1.w));
        }
        #pragma unroll
        for (int nj = 0; nj < 8; nj++) {
            int c0 = n0 + warpN * 64 + nj * 8 + cb;
            __half2 h0 = *reinterpret_cast<__half2*>(&acc[mi][nj][0]); // row r0
            __half2 h1 = *reinterpret_cast<__half2*>(&acc[mi][nj][1]); // row r0+8
            if (MODE == 0) {
                __half* D = (__half*)dst;
                *reinterpret_cast<__half2*>(D + (size_t)r0 * NNEU + c0) = h0;
                *reinterpret_cast<__half2*>(D + (size_t)(r0 + 8) * NNEU + c0) = h1;
            } else if (MODE == 1) {
                __half* D = (__half*)dst;
                float2 f0 = __half22float2(h0);
                float2 f1 = __half22float2(h1);
                float xs0 = aux0[r0], xs1 = aux0[r0 + 8];
                float pq0 = aux1[c0], pq1 = aux1[c0 + 1];
                float sc0 = aux2[c0], sc1 = aux2[c0 + 1];
                float d00 = sqrtf(fmaxf(xs0 + pq0 - 2.f * f0.x, 0.f));
                float d01 = sqrtf(fmaxf(xs0 + pq1 - 2.f * f0.y, 0.f));
                float d10 = sqrtf(fmaxf(xs1 + pq0 - 2.f * f1.x, 0.f));
                float d11 = sqrtf(fmaxf(xs1 + pq1 - 2.f * f1.y, 0.f));
                float e00 = __expf(sc0 / (d00 + 0.1f));
                float e01 = __expf(sc1 / (d01 + 0.1f));
                float e10 = __expf(sc0 / (d10 + 0.1f));
                float e11 = __expf(sc1 / (d11 + 0.1f));
                rs0 += e00 + e01;
                rs1 += e10 + e11;
                *reinterpret_cast<__half2*>(D + (size_t)r0 * NNEU + c0) =
                    __floats2half2_rn(e00, e01);
                *reinterpret_cast<__half2*>(D + (size_t)(r0 + 8) * NNEU + c0) =
                    __floats2half2_rn(e10, e11);
            } else {
                float* D = (float*)dst;
                float2 f0 = __half22float2(h0);
                float2 f1 = __half22float2(h1);
                float b0 = aux1[c0], b1 = aux1[c0 + 1];
                float2 o0 = make_float2(f0.x * iv0 + b0, f0.y * iv0 + b1);
                float2 o1 = make_float2(f1.x * iv1 + b0, f1.y * iv1 + b1);
                *reinterpret_cast<float2*>(D + (size_t)r0 * DIM + c0) = o0;
                *reinterpret_cast<float2*>(D + (size_t)(r0 + 8) * DIM + c0) = o1;
            }
        }
        if (MODE == 1) {
            // reduce over the 4 lanes of the quad (cols), leave on lane&3==0
            rs0 += __shfl_xor_sync(0xffffffffu, rs0, 1);
            rs0 += __shfl_xor_sync(0xffffffffu, rs0, 2);
            rs1 += __shfl_xor_sync(0xffffffffu, rs1, 1);
            rs1 += __shfl_xor_sync(0xffffffffu, rs1, 2);
            if ((lane & 3) == 0) {
                rs_sm[rt0 * 2 + warpN] = rs0;
                rs_sm[(rt0 + 8) * 2 + warpN] = rs1;
            }
        }
    }
    if (MODE == 1) {
        __syncthreads();
        if (tid < 128) {
            float2 v = reinterpret_cast<const float2*>(rs_sm)[tid];
            g_rsp[(size_t)(m0 + tid) * 8 + blockIdx.y] = v.x + v.y;
        }
    }
}

// ============================================================================
// Host launcher — fork/join second stream for conv+VWt overlap with
// rowsq+scores. Stream/events created on first (uncaptured) call only.
// ============================================================================
extern "C" void kernel_launch(void* const* d_in, const int* in_sizes, int n_in,
                              void* d_out, int out_size) {
    (void)in_sizes; (void)n_in; (void)out_size;
    const float* x      = (const float*)d_in[0];
    const float* pos    = (const float*)d_in[1];
    const float* scales = (const float*)d_in[2];
    const float* values = (const float*)d_in[3];
    const float* W      = (const float*)d_in[4];
    const float* b      = (const float*)d_in[5];
    float* out = (float*)d_out;

    static __half* vwt_p = nullptr;
    static __half* E_p   = nullptr;
    static float *xsq_p, *psq_p, *rsp_p;
    static __half *xb_p, *pb_p, *vb_p, *wb_p;
    static cudaStream_t s2;
    static cudaEvent_t eFork, eJoin;
    if (!vwt_p) {
        cudaGetSymbolAddress((void**)&vwt_p, g_vwt);
        cudaGetSymbolAddress((void**)&E_p,   g_E);
        cudaGetSymbolAddress((void**)&xsq_p, g_xsq);
        cudaGetSymbolAddress((void**)&psq_p, g_psq);
        cudaGetSymbolAddress((void**)&rsp_p, g_rsp);
        cudaGetSymbolAddress((void**)&xb_p,  g_xb);
        cudaGetSymbolAddress((void**)&pb_p,  g_pb);
        cudaGetSymbolAddress((void**)&vb_p,  g_vb);
        cudaGetSymbolAddress((void**)&wb_p,  g_wb);
        cudaStreamCreateWithFlags(&s2, cudaStreamNonBlocking);
        cudaEventCreateWithFlags(&eFork, cudaEventDisableTiming);
        cudaEventCreateWithFlags(&eJoin, cudaEventDisableTiming);
        cudaFuncSetAttribute(k_gemm<512, 0>,
            cudaFuncAttributeMaxDynamicSharedMemorySize, SMEM_SZ);
        cudaFuncSetAttribute(k_gemm<512, 1>,
            cudaFuncAttributeMaxDynamicSharedMemorySize, SMEM_SZ);
        cudaFuncSetAttribute(k_gemm<1024, 2>,
            cudaFuncAttributeMaxDynamicSharedMemorySize, SMEM_SZ);
    }

    // fork side stream: conv -> VWt GEMM (independent of x path)
    cudaEventRecord(eFork, 0);
    cudaStreamWaitEvent(s2, eFork, 0);
    k_conv<<<((NNEU * DIM + DIM * DIM) / 4) / 256, 256, 0, s2>>>(values, W);
    k_gemm<512, 0><<<dim3(4, 8), 256, SMEM_SZ, s2>>>(
        wb_p, vb_p, vwt_p, nullptr, nullptr, nullptr);
    cudaEventRecord(eJoin, s2);

    // main stream: rowsq -> scores
    k_rowsq<<<(MTOT + NNEU) / 8, 256>>>(x, pos);
    k_gemm<512, 1><<<dim3(128, 8), 256, SMEM_SZ>>>(
        xb_p, pb_p, E_p, xsq_p, psq_p, scales);

    // join, then out = E @ VWt^T / rowsum + b   (rowsum inlined from g_rsp)
    cudaStreamWaitEvent(0, eJoin, 0);
    k_gemm<1024, 2><<<dim3(128, 4), 256, SMEM_SZ>>>(
        E_p, vwt_p, out, rsp_p, b, nullptr);
}